// round 6
// baseline (speedup 1.0000x reference)
#include <cuda_runtime.h>
#include <cstdint>

// Per-voxel 4th-order tensor transform:
//   C[b,i,j,k,l,v] = sum_{m,n,o,p} a[b,m,i,v] a[b,n,j,v] a[b,o,k,v] a[b,p,l,v] C0[m,n,o,p]
//
// Low-register restructure: never materialize the full 81-float intermediate.
// For each output row i:
//   u[n,o,p]  = sum_m a[m,i] * C0[m,n,o,p]        (27 floats live)
//   for each j:
//     t9[o,p] = sum_n a[n,j] * u[n,o,p]           (9 floats live)
//     for each k,l: C[i,j,k,l] = sum_{o,p} a[o,k] a[p,l] t9[o,p]  -> store
// Same 972 FMA/voxel as before, but peak live set ~55 regs instead of ~105,
// enabling 32 warps/SM instead of 16.

static constexpr int G3 = 64 * 64 * 64;  // 262144 voxels per batch

__global__ void __launch_bounds__(256, 4)
alphaC0_kernel(const float* __restrict__ alpha,
               const float* __restrict__ C0,
               float* __restrict__ out,
               int n_vox) {
    __shared__ float sC0[81];
    int tid = threadIdx.x;
    if (tid < 81) sC0[tid] = C0[tid];
    __syncthreads();

    int v = blockIdx.x * blockDim.x + tid;
    if (v >= n_vox) return;

    int b = v >> 18;            // v / G3
    int s = v & (G3 - 1);       // v % G3

    const float* ap = alpha + (size_t)b * 9 * G3 + s;
    float a[9];                 // a[m*3+i] = a_{m,i}
#pragma unroll
    for (int q = 0; q < 9; q++) a[q] = ap[(size_t)q * G3];

    float* op = out + (size_t)b * 81 * G3 + s;

#pragma unroll
    for (int i = 0; i < 3; i++) {
        // u[n*9 + o*3 + p] = sum_m a[m,i] * C0[m,n,o,p]
        float u[27];
        float a0 = a[0 * 3 + i], a1 = a[1 * 3 + i], a2 = a[2 * 3 + i];
#pragma unroll
        for (int q = 0; q < 27; q++) {
            // q indexes (n,o,p); C0[m,n,o,p] = sC0[m*27 + q]
            u[q] = fmaf(a0, sC0[q],
                   fmaf(a1, sC0[27 + q],
                        a2 * sC0[54 + q]));
        }

#pragma unroll
        for (int j = 0; j < 3; j++) {
            // t9[o*3+p] = sum_n a[n,j] * u[n,o,p]
            float b0 = a[0 * 3 + j], b1 = a[1 * 3 + j], b2 = a[2 * 3 + j];
            float t9[9];
#pragma unroll
            for (int q = 0; q < 9; q++) {
                t9[q] = fmaf(b0, u[q],
                        fmaf(b1, u[9 + q],
                             b2 * u[18 + q]));
            }

#pragma unroll
            for (int k = 0; k < 3; k++) {
                // v[p] = sum_o a[o,k] * t9[o,p]
                float c0 = a[0 * 3 + k], c1 = a[1 * 3 + k], c2 = a[2 * 3 + k];
                float v0 = fmaf(c0, t9[0], fmaf(c1, t9[3], c2 * t9[6]));
                float v1 = fmaf(c0, t9[1], fmaf(c1, t9[4], c2 * t9[7]));
                float v2 = fmaf(c0, t9[2], fmaf(c1, t9[5], c2 * t9[8]));
#pragma unroll
                for (int l = 0; l < 3; l++) {
                    float c = fmaf(a[0 * 3 + l], v0,
                              fmaf(a[1 * 3 + l], v1,
                                   a[2 * 3 + l] * v2));
                    op[(size_t)(((i * 3 + j) * 3 + k) * 3 + l) * G3] = c;
                }
            }
        }
    }
}

extern "C" void kernel_launch(void* const* d_in, const int* in_sizes, int n_in,
                              void* d_out, int out_size) {
    const float* alpha = (const float*)d_in[0];
    const float* C0    = (const float*)d_in[1];
    float* out = (float*)d_out;

    int n_vox = in_sizes[0] / 9;   // B * G^3
    int threads = 256;
    int blocks = (n_vox + threads - 1) / threads;
    alphaC0_kernel<<<blocks, threads>>>(alpha, C0, out, n_vox);
}